// round 16
// baseline (speedup 1.0000x reference)
#include <cuda_runtime.h>
#include <cuda_bf16.h>
#include <cstdint>

#define Bb 2
#define Nn 2048
#define Ee 1024
#define Hh 16
#define Dd 64
#define BH (Bb*Hh)
#define ROWS (Bb*Nn)

// ---------------------------------------------------------------------------
// Scratch — ONLY ever referenced from device code (never passed as kernel args)
// ---------------------------------------------------------------------------
__device__ __nv_bfloat16 g_Qh[BH * Nn * Dd];   // [B,H,N,D], pre-scaled by 1/8
__device__ __nv_bfloat16 g_Ql[BH * Nn * Dd];
__device__ __nv_bfloat16 g_Kh[BH * Nn * Dd];
__device__ __nv_bfloat16 g_Kl[BH * Nn * Dd];
__device__ __nv_bfloat16 g_Vth[BH * Dd * Nn];  // [B,H,D,N] (transposed)
__device__ __nv_bfloat16 g_Vtl[BH * Dd * Nn];
__device__ float g_ctx[ROWS * Ee];             // attention out, [B,N,E] fp32
__device__ __nv_bfloat16 g_wqkvT_h[3 * Ee * Ee];  // [3E][E] (n-major)
__device__ __nv_bfloat16 g_wqkvT_l[3 * Ee * Ee];
__device__ __nv_bfloat16 g_wprojT_h[Ee * Ee];
__device__ __nv_bfloat16 g_wprojT_l[Ee * Ee];

// ---------------------------------------------------------------------------
// helpers
// ---------------------------------------------------------------------------
__device__ __forceinline__ uint32_t smem_u32(const void* p) {
    uint32_t a;
    asm("{ .reg .u64 t; cvta.to.shared.u64 t, %1; cvt.u32.u64 %0, t; }" : "=r"(a) : "l"(p));
    return a;
}

__device__ __forceinline__ void mma_bf16(float* c, const uint32_t* a, const uint32_t* b) {
    asm volatile(
        "mma.sync.aligned.m16n8k16.row.col.f32.bf16.bf16.f32 "
        "{%0,%1,%2,%3}, {%4,%5,%6,%7}, {%8,%9}, {%0,%1,%2,%3};"
        : "+f"(c[0]), "+f"(c[1]), "+f"(c[2]), "+f"(c[3])
        : "r"(a[0]), "r"(a[1]), "r"(a[2]), "r"(a[3]), "r"(b[0]), "r"(b[1]));
}

#define LDMX4(r, addr) \
    asm volatile("ldmatrix.sync.aligned.m8n8.x4.shared.b16 {%0,%1,%2,%3}, [%4];" \
        : "=r"((r)[0]), "=r"((r)[1]), "=r"((r)[2]), "=r"((r)[3]) : "r"(addr))

// fast split: packed bf16x2 hi + residual lo
__device__ __forceinline__ void split2(float x, float y, uint32_t& hi, uint32_t& lo) {
    __nv_bfloat162 h2 = __float22bfloat162_rn(make_float2(x, y));
    hi = *(uint32_t*)&h2;
    const float hx = __uint_as_float(hi << 16);
    const float hy = __uint_as_float(hi & 0xffff0000u);
    __nv_bfloat162 l2 = __float22bfloat162_rn(make_float2(x - hx, y - hy));
    lo = *(uint32_t*)&l2;
}

// ---------------------------------------------------------------------------
// Transpose + split W[1024, NW] -> device-global WT hi/lo [NW][1024] (R10-proven)
// ---------------------------------------------------------------------------
template<int NW, int MODE>
__global__ __launch_bounds__(256)
void conv_wT_kernel(const float* __restrict__ W) {
    __nv_bfloat16* Th = (MODE == 0) ? g_wqkvT_h : g_wprojT_h;
    __nv_bfloat16* Tl = (MODE == 0) ? g_wqkvT_l : g_wprojT_l;
    __shared__ float ts[32][33];
    const int tx = threadIdx.x & 31;
    const int ty = threadIdx.x >> 5;
    const int nb = blockIdx.x * 32;
    const int kb = blockIdx.y * 32;
    #pragma unroll
    for (int i = 0; i < 32; i += 8)
        ts[ty + i][tx] = W[(size_t)(kb + ty + i) * NW + nb + tx];
    __syncthreads();
    #pragma unroll
    for (int i = 0; i < 32; i += 8) {
        const float v = ts[tx][ty + i];
        const __nv_bfloat16 h = __float2bfloat16(v);
        Th[(size_t)(nb + ty + i) * Ee + kb + tx] = h;
        Tl[(size_t)(nb + ty + i) * Ee + kb + tx] = __float2bfloat16(v - __bfloat162float(h));
    }
}

// ---------------------------------------------------------------------------
// HMMA GEMM — R14 body, CTA halved to BM=64 x BN=128, 128 threads (4 warps,
// 1m x 4n), __launch_bounds__(128,4) => 4 CTAs/SM for 2x latency hiding.
// C[4096, NW] = A(fp32) @ WT^T (+bias); AhBh + AhBl + AlBh, fp32 accum.
// BK=16, 18 KB static smem (padded-24, proven conflict-free).
// MODE 0: epilogue -> Qh/Ql(x0.125), Kh/Kl [B,H,N,D], Vth/Vtl [B,H,D,N]
// MODE 1: A = g_ctx, epilogue -> fp32 Cout (+bias)
// ---------------------------------------------------------------------------
template<int NW, int MODE>
__global__ __launch_bounds__(128, 4)
void hmma_gemm(const float* __restrict__ Ain,
               const float* __restrict__ bias, float* __restrict__ Cout)
{
    __shared__ __nv_bfloat16 Ah[64][24], Al[64][24];
    __shared__ __nv_bfloat16 Bh[128][24], Bl[128][24];   // [n][k]

    const int tid  = threadIdx.x;
    const int lane = tid & 31;
    const int wid  = tid >> 5;          // 0..3
    const int gid  = lane >> 2;
    const int tig  = lane & 3;
    const int wn   = wid;               // 4 warps in N, 1 in M

    const int m0 = blockIdx.y * 64;
    const int n0 = blockIdx.x * 128;

    const float* A = (MODE == 0) ? Ain : g_ctx;
    const __nv_bfloat16* WTh = (MODE == 0) ? g_wqkvT_h : g_wprojT_h;
    const __nv_bfloat16* WTl = (MODE == 0) ? g_wqkvT_l : g_wprojT_l;

    const int a_row = tid >> 1;          // 0..63
    const int a_k   = (tid & 1) * 8;     // 0 or 8
    const int b_row = tid;               // 0..127

    float acc[4][4][4] = {};

    #pragma unroll 1
    for (int c = 0; c < 64; ++c) {
        const int k0 = c * 16;
        // global loads (regs die at the smem store, before the MMA block)
        const float4 pa0 = *(const float4*)&A[(size_t)(m0 + a_row) * Ee + k0 + a_k];
        const float4 pa1 = *(const float4*)&A[(size_t)(m0 + a_row) * Ee + k0 + a_k + 4];
        const uint4  pbh0 = *(const uint4*)&WTh[(size_t)(n0 + b_row) * Ee + k0];
        const uint4  pbh1 = *(const uint4*)&WTh[(size_t)(n0 + b_row) * Ee + k0 + 8];
        const uint4  pbl0 = *(const uint4*)&WTl[(size_t)(n0 + b_row) * Ee + k0];
        const uint4  pbl1 = *(const uint4*)&WTl[(size_t)(n0 + b_row) * Ee + k0 + 8];

        __syncthreads();   // previous compute done before smem overwrite

        {
            const float va[8] = {pa0.x, pa0.y, pa0.z, pa0.w, pa1.x, pa1.y, pa1.z, pa1.w};
            __nv_bfloat16 h[8], l[8];
            #pragma unroll
            for (int j = 0; j < 8; ++j) {
                h[j] = __float2bfloat16(va[j]);
                l[j] = __float2bfloat16(va[j] - __bfloat162float(h[j]));
            }
            *(uint4*)&Ah[a_row][a_k] = *(uint4*)h;
            *(uint4*)&Al[a_row][a_k] = *(uint4*)l;
            *(uint4*)&Bh[b_row][0]   = pbh0;
            *(uint4*)&Bh[b_row][8]   = pbh1;
            *(uint4*)&Bl[b_row][0]   = pbl0;
            *(uint4*)&Bl[b_row][8]   = pbl1;
        }
        __syncthreads();

        uint32_t af[4][4], bhf[4][2], blf[4][2];
        #pragma unroll
        for (int mt = 0; mt < 4; ++mt) {
            const int r = mt * 16 + gid;
            af[mt][0] = *(const uint32_t*)&Ah[r][2 * tig];
            af[mt][1] = *(const uint32_t*)&Ah[r + 8][2 * tig];
            af[mt][2] = *(const uint32_t*)&Ah[r][2 * tig + 8];
            af[mt][3] = *(const uint32_t*)&Ah[r + 8][2 * tig + 8];
        }
        #pragma unroll
        for (int nt = 0; nt < 4; ++nt) {
            const int rn = wn * 32 + nt * 8 + gid;
            bhf[nt][0] = *(const uint32_t*)&Bh[rn][2 * tig];
            bhf[nt][1] = *(const uint32_t*)&Bh[rn][2 * tig + 8];
            blf[nt][0] = *(const uint32_t*)&Bl[rn][2 * tig];
            blf[nt][1] = *(const uint32_t*)&Bl[rn][2 * tig + 8];
        }
        #pragma unroll
        for (int mt = 0; mt < 4; ++mt)
            #pragma unroll
            for (int nt = 0; nt < 4; ++nt)
                mma_bf16(acc[mt][nt], af[mt], bhf[nt]);
        #pragma unroll
        for (int mt = 0; mt < 4; ++mt)
            #pragma unroll
            for (int nt = 0; nt < 4; ++nt)
                mma_bf16(acc[mt][nt], af[mt], blf[nt]);
        #pragma unroll
        for (int mt = 0; mt < 4; ++mt) {
            const int r = mt * 16 + gid;
            af[mt][0] = *(const uint32_t*)&Al[r][2 * tig];
            af[mt][1] = *(const uint32_t*)&Al[r + 8][2 * tig];
            af[mt][2] = *(const uint32_t*)&Al[r][2 * tig + 8];
            af[mt][3] = *(const uint32_t*)&Al[r + 8][2 * tig + 8];
        }
        #pragma unroll
        for (int mt = 0; mt < 4; ++mt)
            #pragma unroll
            for (int nt = 0; nt < 4; ++nt)
                mma_bf16(acc[mt][nt], af[mt], bhf[nt]);
    }

    // ---- epilogue (R10-proven logic; wm == 0) ----
    #pragma unroll
    for (int mt = 0; mt < 4; ++mt) {
        #pragma unroll
        for (int hrow = 0; hrow < 2; ++hrow) {
            const int m = m0 + mt * 16 + hrow * 8 + gid;
            #pragma unroll
            for (int nt = 0; nt < 4; ++nt) {
                const int c0 = n0 + wn * 32 + nt * 8 + tig * 2;
                const float r0 = acc[mt][nt][hrow * 2 + 0] + bias[c0];
                const float r1 = acc[mt][nt][hrow * 2 + 1] + bias[c0 + 1];
                if (MODE == 0) {
                    const int sel = c0 >> 10;
                    const int rem = c0 & 1023;
                    const int hh  = rem >> 6;
                    const int d0  = rem & 63;
                    const int b   = m >> 11;
                    const int n   = m & 2047;
                    if (sel == 2) {
                        const size_t vidx = ((size_t)(b * Hh + hh) * Dd + d0) * Nn + n;
                        const __nv_bfloat16 h0 = __float2bfloat16(r0);
                        const __nv_bfloat16 h1 = __float2bfloat16(r1);
                        g_Vth[vidx]      = h0;
                        g_Vtl[vidx]      = __float2bfloat16(r0 - __bfloat162float(h0));
                        g_Vth[vidx + Nn] = h1;
                        g_Vtl[vidx + Nn] = __float2bfloat16(r1 - __bfloat162float(h1));
                    } else {
                        const size_t idx = ((size_t)(b * Hh + hh) * Nn + n) * Dd + d0;
                        const float s0 = (sel == 0) ? r0 * 0.125f : r0;
                        const float s1 = (sel == 0) ? r1 * 0.125f : r1;
                        uint32_t hi, lo;
                        split2(s0, s1, hi, lo);
                        __nv_bfloat16* dh = (sel == 0) ? g_Qh : g_Kh;
                        __nv_bfloat16* dl = (sel == 0) ? g_Ql : g_Kl;
                        *(uint32_t*)&dh[idx] = hi;
                        *(uint32_t*)&dl[idx] = lo;
                    }
                } else {
                    float2 o = {r0, r1};
                    *(float2*)&Cout[(size_t)m * NW + c0] = o;
                }
            }
        }
    }
}

// ---------------------------------------------------------------------------
// HMMA flash attention — R14-proven VERBATIM (299us)
// ---------------------------------------------------------------------------
__global__ __launch_bounds__(128, 3)
void attn_kernel()
{
    __shared__ __nv_bfloat16 Ksh[64][72], Ksl[64][72];
    __shared__ __nv_bfloat16 Vsh[64][72], Vsl[64][72];   // [d][kv]

    const int tid  = threadIdx.x;
    const int lane = tid & 31;
    const int w    = tid >> 5;            // 0..3
    const int gid  = lane >> 2;
    const int tig  = lane & 3;

    const int bh    = blockIdx.y;
    const int qrow0 = blockIdx.x * 64 + w * 16;

    const __nv_bfloat16* Qhp = g_Qh + ((size_t)bh * Nn + qrow0) * Dd;
    const __nv_bfloat16* Qlp = g_Ql + ((size_t)bh * Nn + qrow0) * Dd;
    const __nv_bfloat16* Khg = g_Kh + (size_t)bh * Nn * Dd;
    const __nv_bfloat16* Klg = g_Kl + (size_t)bh * Nn * Dd;
    const __nv_bfloat16* Vhg = g_Vth + (size_t)bh * Dd * Nn;
    const __nv_bfloat16* Vlg = g_Vtl + (size_t)bh * Dd * Nn;

    uint32_t qh[4][4], ql[4][4];
    #pragma unroll
    for (int kc = 0; kc < 4; ++kc) {
        const int d0 = kc * 16 + 2 * tig;
        qh[kc][0] = *(const uint32_t*)&Qhp[(size_t)gid * Dd + d0];
        qh[kc][1] = *(const uint32_t*)&Qhp[(size_t)(gid + 8) * Dd + d0];
        qh[kc][2] = *(const uint32_t*)&Qhp[(size_t)gid * Dd + d0 + 8];
        qh[kc][3] = *(const uint32_t*)&Qhp[(size_t)(gid + 8) * Dd + d0 + 8];
        ql[kc][0] = *(const uint32_t*)&Qlp[(size_t)gid * Dd + d0];
        ql[kc][1] = *(const uint32_t*)&Qlp[(size_t)(gid + 8) * Dd + d0];
        ql[kc][2] = *(const uint32_t*)&Qlp[(size_t)gid * Dd + d0 + 8];
        ql[kc][3] = *(const uint32_t*)&Qlp[(size_t)(gid + 8) * Dd + d0 + 8];
    }

    // ldmatrix per-lane base: sel = lane>>3 picks (row-group, col-half)
    const int sel  = lane >> 3;
    const int lrow = ((sel >> 1) & 1) * 8 + (lane & 7);   // 0..15
    const int lcol = (sel & 1) * 8;                        // 0 or 8
    const uint32_t kh_base = smem_u32(&Ksh[lrow][lcol]);
    const uint32_t kl_base = smem_u32(&Ksl[lrow][lcol]);
    const uint32_t vh_base = smem_u32(&Vsh[lrow][lcol]);
    const uint32_t vl_base = smem_u32(&Vsl[lrow][lcol]);
    // offsets: jj -> +16 rows = 16*144B = 2304; kc -> +16 cols = 32B

    float o[8][4];
    #pragma unroll
    for (int j = 0; j < 8; ++j)
        #pragma unroll
        for (int k = 0; k < 4; ++k)
            o[j][k] = 0.f;
    float m0 = -1e30f, m1 = -1e30f, l0 = 0.f, l1 = 0.f;

    const int ld_r  = tid >> 3;           // 0..15
    const int ld_c  = (tid & 7) * 8;      // 0..56

    #pragma unroll 1
    for (int t0 = 0; t0 < Nn; t0 += 64) {
        __syncthreads();
        #pragma unroll
        for (int i = 0; i < 4; ++i) {
            const int r = ld_r + i * 16;
            *(uint4*)&Ksh[r][ld_c] = *(const uint4*)&Khg[(size_t)(t0 + r) * Dd + ld_c];
            *(uint4*)&Ksl[r][ld_c] = *(const uint4*)&Klg[(size_t)(t0 + r) * Dd + ld_c];
            *(uint4*)&Vsh[r][ld_c] = *(const uint4*)&Vhg[(size_t)r * Nn + t0 + ld_c];
            *(uint4*)&Vsl[r][ld_c] = *(const uint4*)&Vlg[(size_t)r * Nn + t0 + ld_c];
        }
        __syncthreads();

        // ---- S = Q K^T (3 passes, ldmatrix K frags) ----
        float s[8][4];
        #pragma unroll
        for (int j = 0; j < 8; ++j)
            #pragma unroll
            for (int k = 0; k < 4; ++k)
                s[j][k] = 0.f;
        #pragma unroll
        for (int jj = 0; jj < 4; ++jj) {
            #pragma unroll
            for (int kc = 0; kc < 4; ++kc) {
                const uint32_t off = (uint32_t)(jj * 2304 + kc * 32);
                uint32_t bh4[4], bl4[4];
                LDMX4(bh4, kh_base + off);
                LDMX4(bl4, kl_base + off);
                mma_bf16(s[2 * jj],     qh[kc], bh4);
                mma_bf16(s[2 * jj],     qh[kc], bl4);
                mma_bf16(s[2 * jj],     ql[kc], bh4);
                mma_bf16(s[2 * jj + 1], qh[kc], bh4 + 2);
                mma_bf16(s[2 * jj + 1], qh[kc], bl4 + 2);
                mma_bf16(s[2 * jj + 1], ql[kc], bh4 + 2);
            }
        }

        // ---- online softmax (MUFU exp) ----
        float mloc0 = -1e30f, mloc1 = -1e30f;
        #pragma unroll
        for (int j = 0; j < 8; ++j) {
            mloc0 = fmaxf(mloc0, fmaxf(s[j][0], s[j][1]));
            mloc1 = fmaxf(mloc1, fmaxf(s[j][2], s[j][3]));
        }
        mloc0 = fmaxf(mloc0, __shfl_xor_sync(0xffffffffu, mloc0, 1));
        mloc0 = fmaxf(mloc0, __shfl_xor_sync(0xffffffffu, mloc0, 2));
        mloc1 = fmaxf(mloc1, __shfl_xor_sync(0xffffffffu, mloc1, 1));
        mloc1 = fmaxf(mloc1, __shfl_xor_sync(0xffffffffu, mloc1, 2));
        const float mnew0 = fmaxf(m0, mloc0);
        const float mnew1 = fmaxf(m1, mloc1);
        const float corr0 = __expf(m0 - mnew0);
        const float corr1 = __expf(m1 - mnew1);
        #pragma unroll
        for (int j = 0; j < 8; ++j) {
            o[j][0] *= corr0; o[j][1] *= corr0;
            o[j][2] *= corr1; o[j][3] *= corr1;
        }
        float ls0 = 0.f, ls1 = 0.f;
        #pragma unroll
        for (int j = 0; j < 8; ++j) {
            s[j][0] = __expf(s[j][0] - mnew0);
            s[j][1] = __expf(s[j][1] - mnew0);
            s[j][2] = __expf(s[j][2] - mnew1);
            s[j][3] = __expf(s[j][3] - mnew1);
            ls0 += s[j][0] + s[j][1];
            ls1 += s[j][2] + s[j][3];
        }
        ls0 += __shfl_xor_sync(0xffffffffu, ls0, 1);
        ls0 += __shfl_xor_sync(0xffffffffu, ls0, 2);
        ls1 += __shfl_xor_sync(0xffffffffu, ls1, 1);
        ls1 += __shfl_xor_sync(0xffffffffu, ls1, 2);
        l0 = l0 * corr0 + ls0;
        l1 = l1 * corr1 + ls1;
        m0 = mnew0; m1 = mnew1;

        // ---- P -> bf16 hi/lo A-fragments ----
        uint32_t ph[4][4], pl[4][4];
        #pragma unroll
        for (int kc = 0; kc < 4; ++kc) {
            split2(s[2 * kc][0],     s[2 * kc][1],     ph[kc][0], pl[kc][0]);
            split2(s[2 * kc][2],     s[2 * kc][3],     ph[kc][1], pl[kc][1]);
            split2(s[2 * kc + 1][0], s[2 * kc + 1][1], ph[kc][2], pl[kc][2]);
            split2(s[2 * kc + 1][2], s[2 * kc + 1][3], ph[kc][3], pl[kc][3]);
        }

        // ---- O += P V (3 passes, ldmatrix V frags) ----
        #pragma unroll
        for (int jj = 0; jj < 4; ++jj) {
            #pragma unroll
            for (int kc = 0; kc < 4; ++kc) {
                const uint32_t off = (uint32_t)(jj * 2304 + kc * 32);
                uint32_t bh4[4], bl4[4];
                LDMX4(bh4, vh_base + off);
                LDMX4(bl4, vl_base + off);
                mma_bf16(o[2 * jj],     ph[kc], bh4);
                mma_bf16(o[2 * jj],     ph[kc], bl4);
                mma_bf16(o[2 * jj],     pl[kc], bh4);
                mma_bf16(o[2 * jj + 1], ph[kc], bh4 + 2);
                mma_bf16(o[2 * jj + 1], ph[kc], bl4 + 2);
                mma_bf16(o[2 * jj + 1], pl[kc], bh4 + 2);
            }
        }
    }

    // ---- write ctx [B,N,E] fp32 ----
    const float inv0 = 1.f / l0;
    const float inv1 = 1.f / l1;
    const int b  = bh >> 4;
    const int hh = bh & 15;
    const int row0 = qrow0 + gid;
    #pragma unroll
    for (int j = 0; j < 8; ++j) {
        const int col = hh * Dd + j * 8 + 2 * tig;
        float2 o0 = {o[j][0] * inv0, o[j][1] * inv0};
        float2 o1 = {o[j][2] * inv1, o[j][3] * inv1};
        *(float2*)&g_ctx[(size_t)(b * Nn + row0) * Ee + col] = o0;
        *(float2*)&g_ctx[(size_t)(b * Nn + row0 + 8) * Ee + col] = o1;
    }
}

// ---------------------------------------------------------------------------
extern "C" void kernel_launch(void* const* d_in, const int* in_sizes, int n_in,
                              void* d_out, int out_size)
{
    const float* x      = (const float*)d_in[0];
    const float* w_qkv  = (const float*)d_in[1];
    const float* b_qkv  = (const float*)d_in[2];
    const float* w_proj = (const float*)d_in[3];
    const float* b_proj = (const float*)d_in[4];
    float* out = (float*)d_out;

    conv_wT_kernel<3 * Ee, 0><<<dim3(3 * Ee / 32, Ee / 32), 256>>>(w_qkv);
    conv_wT_kernel<Ee, 1><<<dim3(Ee / 32, Ee / 32), 256>>>(w_proj);
    hmma_gemm<3 * Ee, 0><<<dim3(3 * Ee / 128, ROWS / 64), 128>>>(x, b_qkv, nullptr);
    attn_kernel<<<dim3(Nn / 64, BH), 128>>>();
    hmma_gemm<Ee, 1><<<dim3(Ee / 128, ROWS / 64), 128>>>(nullptr, b_proj, out);
}

// round 17
// speedup vs baseline: 1.2040x; 1.2040x over previous
#include <cuda_runtime.h>
#include <cuda_bf16.h>
#include <cstdint>

#define Bb 2
#define Nn 2048
#define Ee 1024
#define Hh 16
#define Dd 64
#define BH (Bb*Hh)
#define ROWS (Bb*Nn)

// ---------------------------------------------------------------------------
// Scratch — ONLY ever referenced from device code (never passed as kernel args)
// ---------------------------------------------------------------------------
__device__ __nv_bfloat16 g_Qh[BH * Nn * Dd];   // [B,H,N,D], pre-scaled by 1/8
__device__ __nv_bfloat16 g_Ql[BH * Nn * Dd];
__device__ __nv_bfloat16 g_Kh[BH * Nn * Dd];
__device__ __nv_bfloat16 g_Kl[BH * Nn * Dd];
__device__ __nv_bfloat16 g_Vth[BH * Dd * Nn];  // [B,H,D,N] (transposed)
__device__ __nv_bfloat16 g_Vtl[BH * Dd * Nn];
__device__ float g_ctx[ROWS * Ee];             // attention out, [B,N,E] fp32
__device__ __nv_bfloat16 g_wqkvT_h[3 * Ee * Ee];  // [3E][E] (n-major)
__device__ __nv_bfloat16 g_wqkvT_l[3 * Ee * Ee];
__device__ __nv_bfloat16 g_wprojT_h[Ee * Ee];
__device__ __nv_bfloat16 g_wprojT_l[Ee * Ee];

// ---------------------------------------------------------------------------
// helpers
// ---------------------------------------------------------------------------
__device__ __forceinline__ uint32_t smem_u32(const void* p) {
    uint32_t a;
    asm("{ .reg .u64 t; cvta.to.shared.u64 t, %1; cvt.u32.u64 %0, t; }" : "=r"(a) : "l"(p));
    return a;
}

__device__ __forceinline__ void mma_bf16(float* c, const uint32_t* a, const uint32_t* b) {
    asm volatile(
        "mma.sync.aligned.m16n8k16.row.col.f32.bf16.bf16.f32 "
        "{%0,%1,%2,%3}, {%4,%5,%6,%7}, {%8,%9}, {%0,%1,%2,%3};"
        : "+f"(c[0]), "+f"(c[1]), "+f"(c[2]), "+f"(c[3])
        : "r"(a[0]), "r"(a[1]), "r"(a[2]), "r"(a[3]), "r"(b[0]), "r"(b[1]));
}

#define LDMX4(r, addr) \
    asm volatile("ldmatrix.sync.aligned.m8n8.x4.shared.b16 {%0,%1,%2,%3}, [%4];" \
        : "=r"((r)[0]), "=r"((r)[1]), "=r"((r)[2]), "=r"((r)[3]) : "r"(addr))

// fast split: packed bf16x2 hi + residual lo
__device__ __forceinline__ void split2(float x, float y, uint32_t& hi, uint32_t& lo) {
    __nv_bfloat162 h2 = __float22bfloat162_rn(make_float2(x, y));
    hi = *(uint32_t*)&h2;
    const float hx = __uint_as_float(hi << 16);
    const float hy = __uint_as_float(hi & 0xffff0000u);
    __nv_bfloat162 l2 = __float22bfloat162_rn(make_float2(x - hx, y - hy));
    lo = *(uint32_t*)&l2;
}

// ---------------------------------------------------------------------------
// Transpose + split W[1024, NW] -> device-global WT hi/lo [NW][1024] (R10-proven)
// ---------------------------------------------------------------------------
template<int NW, int MODE>
__global__ __launch_bounds__(256)
void conv_wT_kernel(const float* __restrict__ W) {
    __nv_bfloat16* Th = (MODE == 0) ? g_wqkvT_h : g_wprojT_h;
    __nv_bfloat16* Tl = (MODE == 0) ? g_wqkvT_l : g_wprojT_l;
    __shared__ float ts[32][33];
    const int tx = threadIdx.x & 31;
    const int ty = threadIdx.x >> 5;
    const int nb = blockIdx.x * 32;
    const int kb = blockIdx.y * 32;
    #pragma unroll
    for (int i = 0; i < 32; i += 8)
        ts[ty + i][tx] = W[(size_t)(kb + ty + i) * NW + nb + tx];
    __syncthreads();
    #pragma unroll
    for (int i = 0; i < 32; i += 8) {
        const float v = ts[tx][ty + i];
        const __nv_bfloat16 h = __float2bfloat16(v);
        Th[(size_t)(nb + ty + i) * Ee + kb + tx] = h;
        Tl[(size_t)(nb + ty + i) * Ee + kb + tx] = __float2bfloat16(v - __bfloat162float(h));
    }
}

// ---------------------------------------------------------------------------
// HMMA GEMM — R14 body (BM=BN=128, BK=16, 256 thr, 24 KB smem, 2 CTA/SM)
// with ldmatrix.x4 fragment loads (48 LDS -> 12 ldmatrix per iter).
// C[4096, NW] = A(fp32) @ WT^T (+bias); AhBh + AhBl + AlBh, fp32 accum.
// MODE 0: epilogue -> Qh/Ql(x0.125), Kh/Kl [B,H,N,D], Vth/Vtl [B,H,D,N]
// MODE 1: A = g_ctx, epilogue -> fp32 Cout (+bias)
// ---------------------------------------------------------------------------
template<int NW, int MODE>
__global__ __launch_bounds__(256, 2)
void hmma_gemm(const float* __restrict__ Ain,
               const float* __restrict__ bias, float* __restrict__ Cout)
{
    __shared__ __nv_bfloat16 Ah[128][24], Al[128][24];
    __shared__ __nv_bfloat16 Bh[128][24], Bl[128][24];   // [n][k]

    const int tid  = threadIdx.x;
    const int lane = tid & 31;
    const int wid  = tid >> 5;
    const int gid  = lane >> 2;
    const int tig  = lane & 3;
    const int wm   = wid & 1;
    const int wn   = wid >> 1;

    const int m0 = blockIdx.y * 128;
    const int n0 = blockIdx.x * 128;

    const float* A = (MODE == 0) ? Ain : g_ctx;
    const __nv_bfloat16* WTh = (MODE == 0) ? g_wqkvT_h : g_wprojT_h;
    const __nv_bfloat16* WTl = (MODE == 0) ? g_wqkvT_l : g_wprojT_l;

    const int a_row = tid >> 1;
    const int a_k   = (tid & 1) * 8;

    // ldmatrix per-lane addressing (attention-proven pattern)
    const int sel  = lane >> 3;
    const int lr   = ((sel >> 1) & 1) * 8 + (lane & 7);
    const int lc   = (sel & 1) * 8;
    const uint32_t aBaseH = smem_u32(&Ah[wm * 64 + lr][lc]);   // + mt*768
    const uint32_t aBaseL = smem_u32(&Al[wm * 64 + lr][lc]);
    const uint32_t bBaseH = smem_u32(&Bh[wn * 32 + lr][lc]);   // + p*768
    const uint32_t bBaseL = smem_u32(&Bl[wn * 32 + lr][lc]);

    float acc[4][4][4] = {};

    #pragma unroll 1
    for (int c = 0; c < 64; ++c) {
        const int k0 = c * 16;
        const float4 pa0 = *(const float4*)&A[(size_t)(m0 + a_row) * Ee + k0 + a_k];
        const float4 pa1 = *(const float4*)&A[(size_t)(m0 + a_row) * Ee + k0 + a_k + 4];
        const uint4  pbh = *(const uint4*)&WTh[(size_t)(n0 + a_row) * Ee + k0 + a_k];
        const uint4  pbl = *(const uint4*)&WTl[(size_t)(n0 + a_row) * Ee + k0 + a_k];

        __syncthreads();

        {
            const float va[8] = {pa0.x, pa0.y, pa0.z, pa0.w, pa1.x, pa1.y, pa1.z, pa1.w};
            __nv_bfloat16 h[8], l[8];
            #pragma unroll
            for (int j = 0; j < 8; ++j) {
                h[j] = __float2bfloat16(va[j]);
                l[j] = __float2bfloat16(va[j] - __bfloat162float(h[j]));
            }
            *(uint4*)&Ah[a_row][a_k] = *(uint4*)h;
            *(uint4*)&Al[a_row][a_k] = *(uint4*)l;
            *(uint4*)&Bh[a_row][a_k] = pbh;
            *(uint4*)&Bl[a_row][a_k] = pbl;
        }
        __syncthreads();

        uint32_t af[4][4], bhf[4][2], blf[4][2];
        #pragma unroll
        for (int mt = 0; mt < 4; ++mt) {
            uint32_t t[4];
            LDMX4(t, aBaseH + (uint32_t)(mt * 768));
            af[mt][0] = t[0]; af[mt][1] = t[2]; af[mt][2] = t[1]; af[mt][3] = t[3];
        }
        #pragma unroll
        for (int p = 0; p < 2; ++p) {
            uint32_t t[4];
            LDMX4(t, bBaseH + (uint32_t)(p * 768));
            bhf[2 * p][0] = t[0]; bhf[2 * p][1] = t[1];
            bhf[2 * p + 1][0] = t[2]; bhf[2 * p + 1][1] = t[3];
            uint32_t u[4];
            LDMX4(u, bBaseL + (uint32_t)(p * 768));
            blf[2 * p][0] = u[0]; blf[2 * p][1] = u[1];
            blf[2 * p + 1][0] = u[2]; blf[2 * p + 1][1] = u[3];
        }
        #pragma unroll
        for (int mt = 0; mt < 4; ++mt)
            #pragma unroll
            for (int nt = 0; nt < 4; ++nt)
                mma_bf16(acc[mt][nt], af[mt], bhf[nt]);
        #pragma unroll
        for (int mt = 0; mt < 4; ++mt)
            #pragma unroll
            for (int nt = 0; nt < 4; ++nt)
                mma_bf16(acc[mt][nt], af[mt], blf[nt]);
        #pragma unroll
        for (int mt = 0; mt < 4; ++mt) {
            uint32_t t[4];
            LDMX4(t, aBaseL + (uint32_t)(mt * 768));
            af[mt][0] = t[0]; af[mt][1] = t[2]; af[mt][2] = t[1]; af[mt][3] = t[3];
        }
        #pragma unroll
        for (int mt = 0; mt < 4; ++mt)
            #pragma unroll
            for (int nt = 0; nt < 4; ++nt)
                mma_bf16(acc[mt][nt], af[mt], bhf[nt]);
    }

    // ---- epilogue (R10-proven) ----
    #pragma unroll
    for (int mt = 0; mt < 4; ++mt) {
        #pragma unroll
        for (int hrow = 0; hrow < 2; ++hrow) {
            const int m = m0 + wm * 64 + mt * 16 + hrow * 8 + gid;
            #pragma unroll
            for (int nt = 0; nt < 4; ++nt) {
                const int c0 = n0 + wn * 32 + nt * 8 + tig * 2;
                const float r0 = acc[mt][nt][hrow * 2 + 0] + bias[c0];
                const float r1 = acc[mt][nt][hrow * 2 + 1] + bias[c0 + 1];
                if (MODE == 0) {
                    const int sel2 = c0 >> 10;
                    const int rem = c0 & 1023;
                    const int hh  = rem >> 6;
                    const int d0  = rem & 63;
                    const int b   = m >> 11;
                    const int n   = m & 2047;
                    if (sel2 == 2) {
                        const size_t vidx = ((size_t)(b * Hh + hh) * Dd + d0) * Nn + n;
                        const __nv_bfloat16 h0 = __float2bfloat16(r0);
                        const __nv_bfloat16 h1 = __float2bfloat16(r1);
                        g_Vth[vidx]      = h0;
                        g_Vtl[vidx]      = __float2bfloat16(r0 - __bfloat162float(h0));
                        g_Vth[vidx + Nn] = h1;
                        g_Vtl[vidx + Nn] = __float2bfloat16(r1 - __bfloat162float(h1));
                    } else {
                        const size_t idx = ((size_t)(b * Hh + hh) * Nn + n) * Dd + d0;
                        const float s0 = (sel2 == 0) ? r0 * 0.125f : r0;
                        const float s1 = (sel2 == 0) ? r1 * 0.125f : r1;
                        uint32_t hi, lo;
                        split2(s0, s1, hi, lo);
                        __nv_bfloat16* dh = (sel2 == 0) ? g_Qh : g_Kh;
                        __nv_bfloat16* dl = (sel2 == 0) ? g_Ql : g_Kl;
                        *(uint32_t*)&dh[idx] = hi;
                        *(uint32_t*)&dl[idx] = lo;
                    }
                } else {
                    float2 o = {r0, r1};
                    *(float2*)&Cout[(size_t)m * NW + c0] = o;
                }
            }
        }
    }
}

// ---------------------------------------------------------------------------
// HMMA flash attention — R14-proven VERBATIM (299us)
// ---------------------------------------------------------------------------
__global__ __launch_bounds__(128, 3)
void attn_kernel()
{
    __shared__ __nv_bfloat16 Ksh[64][72], Ksl[64][72];
    __shared__ __nv_bfloat16 Vsh[64][72], Vsl[64][72];   // [d][kv]

    const int tid  = threadIdx.x;
    const int lane = tid & 31;
    const int w    = tid >> 5;            // 0..3
    const int gid  = lane >> 2;
    const int tig  = lane & 3;

    const int bh    = blockIdx.y;
    const int qrow0 = blockIdx.x * 64 + w * 16;

    const __nv_bfloat16* Qhp = g_Qh + ((size_t)bh * Nn + qrow0) * Dd;
    const __nv_bfloat16* Qlp = g_Ql + ((size_t)bh * Nn + qrow0) * Dd;
    const __nv_bfloat16* Khg = g_Kh + (size_t)bh * Nn * Dd;
    const __nv_bfloat16* Klg = g_Kl + (size_t)bh * Nn * Dd;
    const __nv_bfloat16* Vhg = g_Vth + (size_t)bh * Dd * Nn;
    const __nv_bfloat16* Vlg = g_Vtl + (size_t)bh * Dd * Nn;

    uint32_t qh[4][4], ql[4][4];
    #pragma unroll
    for (int kc = 0; kc < 4; ++kc) {
        const int d0 = kc * 16 + 2 * tig;
        qh[kc][0] = *(const uint32_t*)&Qhp[(size_t)gid * Dd + d0];
        qh[kc][1] = *(const uint32_t*)&Qhp[(size_t)(gid + 8) * Dd + d0];
        qh[kc][2] = *(const uint32_t*)&Qhp[(size_t)gid * Dd + d0 + 8];
        qh[kc][3] = *(const uint32_t*)&Qhp[(size_t)(gid + 8) * Dd + d0 + 8];
        ql[kc][0] = *(const uint32_t*)&Qlp[(size_t)gid * Dd + d0];
        ql[kc][1] = *(const uint32_t*)&Qlp[(size_t)(gid + 8) * Dd + d0];
        ql[kc][2] = *(const uint32_t*)&Qlp[(size_t)gid * Dd + d0 + 8];
        ql[kc][3] = *(const uint32_t*)&Qlp[(size_t)(gid + 8) * Dd + d0 + 8];
    }

    const int sel  = lane >> 3;
    const int lrow = ((sel >> 1) & 1) * 8 + (lane & 7);   // 0..15
    const int lcol = (sel & 1) * 8;                        // 0 or 8
    const uint32_t kh_base = smem_u32(&Ksh[lrow][lcol]);
    const uint32_t kl_base = smem_u32(&Ksl[lrow][lcol]);
    const uint32_t vh_base = smem_u32(&Vsh[lrow][lcol]);
    const uint32_t vl_base = smem_u32(&Vsl[lrow][lcol]);

    float o[8][4];
    #pragma unroll
    for (int j = 0; j < 8; ++j)
        #pragma unroll
        for (int k = 0; k < 4; ++k)
            o[j][k] = 0.f;
    float m0 = -1e30f, m1 = -1e30f, l0 = 0.f, l1 = 0.f;

    const int ld_r  = tid >> 3;           // 0..15
    const int ld_c  = (tid & 7) * 8;      // 0..56

    #pragma unroll 1
    for (int t0 = 0; t0 < Nn; t0 += 64) {
        __syncthreads();
        #pragma unroll
        for (int i = 0; i < 4; ++i) {
            const int r = ld_r + i * 16;
            *(uint4*)&Ksh[r][ld_c] = *(const uint4*)&Khg[(size_t)(t0 + r) * Dd + ld_c];
            *(uint4*)&Ksl[r][ld_c] = *(const uint4*)&Klg[(size_t)(t0 + r) * Dd + ld_c];
            *(uint4*)&Vsh[r][ld_c] = *(const uint4*)&Vhg[(size_t)r * Nn + t0 + ld_c];
            *(uint4*)&Vsl[r][ld_c] = *(const uint4*)&Vlg[(size_t)r * Nn + t0 + ld_c];
        }
        __syncthreads();

        float s[8][4];
        #pragma unroll
        for (int j = 0; j < 8; ++j)
            #pragma unroll
            for (int k = 0; k < 4; ++k)
                s[j][k] = 0.f;
        #pragma unroll
        for (int jj = 0; jj < 4; ++jj) {
            #pragma unroll
            for (int kc = 0; kc < 4; ++kc) {
                const uint32_t off = (uint32_t)(jj * 2304 + kc * 32);
                uint32_t bh4[4], bl4[4];
                LDMX4(bh4, kh_base + off);
                LDMX4(bl4, kl_base + off);
                mma_bf16(s[2 * jj],     qh[kc], bh4);
                mma_bf16(s[2 * jj],     qh[kc], bl4);
                mma_bf16(s[2 * jj],     ql[kc], bh4);
                mma_bf16(s[2 * jj + 1], qh[kc], bh4 + 2);
                mma_bf16(s[2 * jj + 1], qh[kc], bl4 + 2);
                mma_bf16(s[2 * jj + 1], ql[kc], bh4 + 2);
            }
        }

        float mloc0 = -1e30f, mloc1 = -1e30f;
        #pragma unroll
        for (int j = 0; j < 8; ++j) {
            mloc0 = fmaxf(mloc0, fmaxf(s[j][0], s[j][1]));
            mloc1 = fmaxf(mloc1, fmaxf(s[j][2], s[j][3]));
        }
        mloc0 = fmaxf(mloc0, __shfl_xor_sync(0xffffffffu, mloc0, 1));
        mloc0 = fmaxf(mloc0, __shfl_xor_sync(0xffffffffu, mloc0, 2));
        mloc1 = fmaxf(mloc1, __shfl_xor_sync(0xffffffffu, mloc1, 1));
        mloc1 = fmaxf(mloc1, __shfl_xor_sync(0xffffffffu, mloc1, 2));
        const float mnew0 = fmaxf(m0, mloc0);
        const float mnew1 = fmaxf(m1, mloc1);
        const float corr0 = __expf(m0 - mnew0);
        const float corr1 = __expf(m1 - mnew1);
        #pragma unroll
        for (int j = 0; j < 8; ++j) {
            o[j][0] *= corr0; o[j][1] *= corr0;
            o[j][2] *= corr1; o[j][3] *= corr1;
        }
        float ls0 = 0.f, ls1 = 0.f;
        #pragma unroll
        for (int j = 0; j < 8; ++j) {
            s[j][0] = __expf(s[j][0] - mnew0);
            s[j][1] = __expf(s[j][1] - mnew0);
            s[j][2] = __expf(s[j][2] - mnew1);
            s[j][3] = __expf(s[j][3] - mnew1);
            ls0 += s[j][0] + s[j][1];
            ls1 += s[j][2] + s[j][3];
        }
        ls0 += __shfl_xor_sync(0xffffffffu, ls0, 1);
        ls0 += __shfl_xor_sync(0xffffffffu, ls0, 2);
        ls1 += __shfl_xor_sync(0xffffffffu, ls1, 1);
        ls1 += __shfl_xor_sync(0xffffffffu, ls1, 2);
        l0 = l0 * corr0 + ls0;
        l1 = l1 * corr1 + ls1;
        m0 = mnew0; m1 = mnew1;

        uint32_t ph[4][4], pl[4][4];
        #pragma unroll
        for (int kc = 0; kc < 4; ++kc) {
            split2(s[2 * kc][0],     s[2 * kc][1],     ph[kc][0], pl[kc][0]);
            split2(s[2 * kc][2],     s[2 * kc][3],     ph[kc][1], pl[kc][1]);
            split2(s[2 * kc + 1][0], s[2 * kc + 1][1], ph[kc][2], pl[kc][2]);
            split2(s[2 * kc + 1][2], s[2 * kc + 1][3], ph[kc][3], pl[kc][3]);
        }

        #pragma unroll
        for (int jj = 0; jj < 4; ++jj) {
            #pragma unroll
            for (int kc = 0; kc < 4; ++kc) {
                const uint32_t off = (uint32_t)(jj * 2304 + kc * 32);
                uint32_t bh4[4], bl4[4];
                LDMX4(bh4, vh_base + off);
                LDMX4(bl4, vl_base + off);
                mma_bf16(o[2 * jj],     ph[kc], bh4);
                mma_bf16(o[2 * jj],     ph[kc], bl4);
                mma_bf16(o[2 * jj],     pl[kc], bh4);
                mma_bf16(o[2 * jj + 1], ph[kc], bh4 + 2);
                mma_bf16(o[2 * jj + 1], ph[kc], bl4 + 2);
                mma_bf16(o[2 * jj + 1], pl[kc], bh4 + 2);
            }
        }
    }

    const float inv0 = 1.f / l0;
    const float inv1 = 1.f / l1;
    const int b  = bh >> 4;
    const int hh = bh & 15;
    const int row0 = qrow0 + gid;
    #pragma unroll
    for (int j = 0; j < 8; ++j) {
        const int col = hh * Dd + j * 8 + 2 * tig;
        float2 o0 = {o[j][0] * inv0, o[j][1] * inv0};
        float2 o1 = {o[j][2] * inv1, o[j][3] * inv1};
        *(float2*)&g_ctx[(size_t)(b * Nn + row0) * Ee + col] = o0;
        *(float2*)&g_ctx[(size_t)(b * Nn + row0 + 8) * Ee + col] = o1;
    }
}

// ---------------------------------------------------------------------------
extern "C" void kernel_launch(void* const* d_in, const int* in_sizes, int n_in,
                              void* d_out, int out_size)
{
    const float* x      = (const float*)d_in[0];
    const float* w_qkv  = (const float*)d_in[1];
    const float* b_qkv  = (const float*)d_in[2];
    const float* w_proj = (const float*)d_in[3];
    const float* b_proj = (const float*)d_in[4];
    float* out = (float*)d_out;

    conv_wT_kernel<3 * Ee, 0><<<dim3(3 * Ee / 32, Ee / 32), 256>>>(w_qkv);
    conv_wT_kernel<Ee, 1><<<dim3(Ee / 32, Ee / 32), 256>>>(w_proj);
    hmma_gemm<3 * Ee, 0><<<dim3(3 * Ee / 128, ROWS / 128), 256>>>(x, b_qkv, nullptr);
    attn_kernel<<<dim3(Nn / 64, BH), 128>>>();
    hmma_gemm<Ee, 1><<<dim3(Ee / 128, ROWS / 128), 256>>>(nullptr, b_proj, out);
}